// round 2
// baseline (speedup 1.0000x reference)
#include <cuda_runtime.h>
#include <math.h>

// Problem dims
constexpr int Bb  = 8;
constexpr int Ss  = 256;
constexpr int Cc  = 256;
constexpr int Vk  = 64;
constexpr int NBS = Bb * Ss;   // 2048 rows of ctx
constexpr int NN  = Cc * Vk;   // 16384 = flattened (j,k)

// Scratch (device globals: allocation-free per harness rules)
__device__ float g_W2[(size_t)Cc * Cc * Vk];   // W with linmul folded on diagonal (16.8 MB)
__device__ float g_tmp[(size_t)NBS * NN];      // stage-1 result (134 MB)
__device__ float g_Arow[NBS * Vk];             // per-(b,z) additive term
__device__ float g_Beta[NBS * Vk];             // per-(b,s) additive term (+ all biases except lin1_b)

// ---------------------------------------------------------------------------
// W2[i,j,k] = W[i,j,k] + (i==j) * linmul_w[k,j]
// ---------------------------------------------------------------------------
__global__ void k_w2(const float* __restrict__ W, const float* __restrict__ lmw) {
    int idx4 = blockIdx.x * 256 + threadIdx.x;          // 0 .. 1048575 (float4 granules)
    float4 w = ((const float4*)W)[idx4];
    int e0 = idx4 * 4;
    int k0 = e0 & 63;
    int j  = (e0 >> 6) & 255;
    int i  = e0 >> 14;
    if (i == j) {
        w.x += lmw[(k0 + 0) * Cc + j];
        w.y += lmw[(k0 + 1) * Cc + j];
        w.z += lmw[(k0 + 2) * Cc + j];
        w.w += lmw[(k0 + 3) * Cc + j];
    }
    ((float4*)g_W2)[idx4] = w;
}

// ---------------------------------------------------------------------------
// Arow[r,k] = ctx[r,:]·(lin1_w[k,:]+lindiff_w[k,:]) + lin1_b[k]
// Beta[r,k] = ctx[r,:]·(lin2_w[k,:]-lindiff_w[k,:]) + lin2_b+linmul_b+lindiff_b+bias
// one block per row r = b*S+z (or b*S+s)
// ---------------------------------------------------------------------------
__global__ void k_rowcol(const float* __restrict__ ctx,
                         const float* __restrict__ l1w, const float* __restrict__ l1b,
                         const float* __restrict__ l2w, const float* __restrict__ l2b,
                         const float* __restrict__ lmb,
                         const float* __restrict__ ldw, const float* __restrict__ ldb,
                         const float* __restrict__ bias) {
    __shared__ float xs[Cc];
    int r = blockIdx.x;
    int t = threadIdx.x;                 // 128 threads
    for (int c = t; c < Cc; c += 128) xs[c] = ctx[r * Cc + c];
    __syncthreads();
    if (t < 64) {
        int k = t;
        float acc = 0.f;
        #pragma unroll 8
        for (int c = 0; c < Cc; ++c)
            acc = fmaf(xs[c], l1w[k * Cc + c] + ldw[k * Cc + c], acc);
        g_Arow[r * Vk + k] = acc + l1b[k];
    } else {
        int k = t - 64;
        float acc = 0.f;
        #pragma unroll 8
        for (int c = 0; c < Cc; ++c)
            acc = fmaf(xs[c], l2w[k * Cc + c] - ldw[k * Cc + c], acc);
        g_Beta[r * Vk + k] = acc + l2b[k] + lmb[k] + ldb[k] + bias[k];
    }
}

// ---------------------------------------------------------------------------
// K1: g_tmp(2048 x 16384) = ctx(2048 x 256) @ g_W2(256 x 16384)
// 128x128x16 tiles, 256 threads, 8x8 per thread, double-buffered smem
// ---------------------------------------------------------------------------
__global__ __launch_bounds__(256) void k_gemm1(const float* __restrict__ A) {
    constexpr int BM = 128, BN = 128, BK = 16, NT = Cc / BK;
    __shared__ float As[2][BK][BM];
    __shared__ float Bs[2][BK][BN];

    const int tid = threadIdx.x;
    const int tr  = tid >> 4;            // 0..15
    const int tc  = tid & 15;            // 0..15
    const int rowBase = blockIdx.y * BM;
    const int colBase = blockIdx.x * BN;

    float acc[8][8];
    #pragma unroll
    for (int m = 0; m < 8; ++m)
        #pragma unroll
        for (int n = 0; n < 8; ++n) acc[m][n] = 0.f;

    float4 ra[2], rb[2];

    // prologue: tile 0
    #pragma unroll
    for (int q = 0; q < 2; ++q) {
        int s = tid + q * 256;
        ra[q] = *(const float4*)&A[(size_t)(rowBase + (s >> 2)) * Cc + ((s & 3) << 2)];
        rb[q] = *(const float4*)&g_W2[(size_t)(s >> 5) * NN + colBase + ((s & 31) << 2)];
    }
    #pragma unroll
    for (int q = 0; q < 2; ++q) {
        int s = tid + q * 256;
        int rA = s >> 2, cA = (s & 3) << 2;
        As[0][cA + 0][rA] = ra[q].x;
        As[0][cA + 1][rA] = ra[q].y;
        As[0][cA + 2][rA] = ra[q].z;
        As[0][cA + 3][rA] = ra[q].w;
        *(float4*)&Bs[0][s >> 5][(s & 31) << 2] = rb[q];
    }
    __syncthreads();

    int buf = 0;
    for (int t = 0; t < NT; ++t) {
        if (t + 1 < NT) {
            #pragma unroll
            for (int q = 0; q < 2; ++q) {
                int s = tid + q * 256;
                ra[q] = *(const float4*)&A[(size_t)(rowBase + (s >> 2)) * Cc + (t + 1) * BK + ((s & 3) << 2)];
                rb[q] = *(const float4*)&g_W2[(size_t)((t + 1) * BK + (s >> 5)) * NN + colBase + ((s & 31) << 2)];
            }
        }
        #pragma unroll
        for (int kk = 0; kk < BK; ++kk) {
            float a[8], b[8];
            *(float4*)&a[0] = *(const float4*)&As[buf][kk][tr * 8];
            *(float4*)&a[4] = *(const float4*)&As[buf][kk][tr * 8 + 4];
            *(float4*)&b[0] = *(const float4*)&Bs[buf][kk][tc * 8];
            *(float4*)&b[4] = *(const float4*)&Bs[buf][kk][tc * 8 + 4];
            #pragma unroll
            for (int m = 0; m < 8; ++m)
                #pragma unroll
                for (int n = 0; n < 8; ++n)
                    acc[m][n] = fmaf(a[m], b[n], acc[m][n]);
        }
        if (t + 1 < NT) {
            int nb = buf ^ 1;
            #pragma unroll
            for (int q = 0; q < 2; ++q) {
                int s = tid + q * 256;
                int rA = s >> 2, cA = (s & 3) << 2;
                As[nb][cA + 0][rA] = ra[q].x;
                As[nb][cA + 1][rA] = ra[q].y;
                As[nb][cA + 2][rA] = ra[q].z;
                As[nb][cA + 3][rA] = ra[q].w;
                *(float4*)&Bs[nb][s >> 5][(s & 31) << 2] = rb[q];
            }
            __syncthreads();
            buf = nb;
        }
    }

    #pragma unroll
    for (int m = 0; m < 8; ++m) {
        size_t off = (size_t)(rowBase + tr * 8 + m) * NN + colBase + tc * 8;
        *(float4*)&g_tmp[off]     = make_float4(acc[m][0], acc[m][1], acc[m][2], acc[m][3]);
        *(float4*)&g_tmp[off + 4] = make_float4(acc[m][4], acc[m][5], acc[m][6], acc[m][7]);
    }
}

// ---------------------------------------------------------------------------
// K2: per (b,s) block: out[b,s,:,:](256x64) =
//     tanh( ctx[b](256x256) @ g_tmp[b,s](256x64) + Arow[b,z,:] + Beta[b,s,:] )
// 256x64x16 tiles, 256 threads, 8x8 per thread, double-buffered smem
// ---------------------------------------------------------------------------
__global__ __launch_bounds__(256) void k_gemm2(const float* __restrict__ ctx,
                                               float* __restrict__ out) {
    constexpr int BM = 256, BN = 64, BK = 16, NT = Cc / BK;
    __shared__ float As[2][BK][BM];
    __shared__ float Bs[2][BK][BN];
    __shared__ float beta_s[Vk];

    const int tid = threadIdx.x;
    const int tr  = tid >> 3;            // 0..31 (z-tile)
    const int tc  = tid & 7;             // 0..7  (k-tile)
    const int bs  = blockIdx.x;          // 0..2047 = b*S+s
    const int b   = bs >> 8;

    const float* Ab = ctx + (size_t)b * Ss * Cc;
    const float* Bm = g_tmp + (size_t)bs * NN;

    if (tid < Vk) beta_s[tid] = g_Beta[bs * Vk + tid];

    float acc[8][8];
    #pragma unroll
    for (int m = 0; m < 8; ++m)
        #pragma unroll
        for (int n = 0; n < 8; ++n) acc[m][n] = 0.f;

    float4 ra[4], rb;

    // prologue: tile 0
    #pragma unroll
    for (int q = 0; q < 4; ++q) {
        int s = tid + q * 256;
        ra[q] = *(const float4*)&Ab[(size_t)(s >> 2) * Cc + ((s & 3) << 2)];
    }
    rb = *(const float4*)&Bm[(size_t)(tid >> 4) * Vk + ((tid & 15) << 2)];
    #pragma unroll
    for (int q = 0; q < 4; ++q) {
        int s = tid + q * 256;
        int rA = s >> 2, cA = (s & 3) << 2;
        As[0][cA + 0][rA] = ra[q].x;
        As[0][cA + 1][rA] = ra[q].y;
        As[0][cA + 2][rA] = ra[q].z;
        As[0][cA + 3][rA] = ra[q].w;
    }
    *(float4*)&Bs[0][tid >> 4][(tid & 15) << 2] = rb;
    __syncthreads();

    int buf = 0;
    for (int t = 0; t < NT; ++t) {
        if (t + 1 < NT) {
            #pragma unroll
            for (int q = 0; q < 4; ++q) {
                int s = tid + q * 256;
                ra[q] = *(const float4*)&Ab[(size_t)(s >> 2) * Cc + (t + 1) * BK + ((s & 3) << 2)];
            }
            rb = *(const float4*)&Bm[(size_t)((t + 1) * BK + (tid >> 4)) * Vk + ((tid & 15) << 2)];
        }
        #pragma unroll
        for (int kk = 0; kk < BK; ++kk) {
            float a[8], bv[8];
            *(float4*)&a[0]  = *(const float4*)&As[buf][kk][tr * 8];
            *(float4*)&a[4]  = *(const float4*)&As[buf][kk][tr * 8 + 4];
            *(float4*)&bv[0] = *(const float4*)&Bs[buf][kk][tc * 8];
            *(float4*)&bv[4] = *(const float4*)&Bs[buf][kk][tc * 8 + 4];
            #pragma unroll
            for (int m = 0; m < 8; ++m)
                #pragma unroll
                for (int n = 0; n < 8; ++n)
                    acc[m][n] = fmaf(a[m], bv[n], acc[m][n]);
        }
        if (t + 1 < NT) {
            int nb = buf ^ 1;
            #pragma unroll
            for (int q = 0; q < 4; ++q) {
                int s = tid + q * 256;
                int rA = s >> 2, cA = (s & 3) << 2;
                As[nb][cA + 0][rA] = ra[q].x;
                As[nb][cA + 1][rA] = ra[q].y;
                As[nb][cA + 2][rA] = ra[q].z;
                As[nb][cA + 3][rA] = ra[q].w;
            }
            *(float4*)&Bs[nb][tid >> 4][(tid & 15) << 2] = rb;
            __syncthreads();
            buf = nb;
        }
    }

    // epilogue: + Arow[b,z,k] + Beta[b,s,k] (+biases already folded), tanh, store
    #pragma unroll
    for (int m = 0; m < 8; ++m) {
        int z = tr * 8 + m;
        size_t arOff = (size_t)(b * Ss + z) * Vk + tc * 8;
        float4 ar0 = *(const float4*)&g_Arow[arOff];
        float4 ar1 = *(const float4*)&g_Arow[arOff + 4];
        float4 o0, o1;
        o0.x = tanhf(acc[m][0] + ar0.x + beta_s[tc * 8 + 0]);
        o0.y = tanhf(acc[m][1] + ar0.y + beta_s[tc * 8 + 1]);
        o0.z = tanhf(acc[m][2] + ar0.z + beta_s[tc * 8 + 2]);
        o0.w = tanhf(acc[m][3] + ar0.w + beta_s[tc * 8 + 3]);
        o1.x = tanhf(acc[m][4] + ar1.x + beta_s[tc * 8 + 4]);
        o1.y = tanhf(acc[m][5] + ar1.y + beta_s[tc * 8 + 5]);
        o1.z = tanhf(acc[m][6] + ar1.z + beta_s[tc * 8 + 6]);
        o1.w = tanhf(acc[m][7] + ar1.w + beta_s[tc * 8 + 7]);
        size_t oOff = ((size_t)bs * Ss + z) * Vk + tc * 8;
        *(float4*)&out[oOff]     = o0;
        *(float4*)&out[oOff + 4] = o1;
    }
}

// ---------------------------------------------------------------------------
extern "C" void kernel_launch(void* const* d_in, const int* in_sizes, int n_in,
                              void* d_out, int out_size) {
    const float* ctx       = (const float*)d_in[0];
    const float* W         = (const float*)d_in[1];
    const float* bias      = (const float*)d_in[2];
    const float* lin1_w    = (const float*)d_in[3];
    const float* lin1_b    = (const float*)d_in[4];
    const float* lin2_w    = (const float*)d_in[5];
    const float* lin2_b    = (const float*)d_in[6];
    const float* linmul_w  = (const float*)d_in[7];
    const float* linmul_b  = (const float*)d_in[8];
    const float* lindiff_w = (const float*)d_in[9];
    const float* lindiff_b = (const float*)d_in[10];
    float* out = (float*)d_out;

    // fold linmul into W diagonal
    k_w2<<<(Cc * Cc * Vk) / (256 * 4), 256>>>(W, linmul_w);
    // per-row additive terms (all small GEMVs fused)
    k_rowcol<<<NBS, 128>>>(ctx, lin1_w, lin1_b, lin2_w, lin2_b,
                           linmul_b, lindiff_w, lindiff_b, bias);
    // stage 1: tmp[bs, (j,k)] = ctx @ W2
    k_gemm1<<<dim3(NN / 128, NBS / 128), 256>>>(ctx);
    // stage 2: out[b,s,z,k] = tanh(ctx[b] @ tmp[b,s] + Arow + Beta)
    k_gemm2<<<NBS, 256>>>(ctx, out);
}